// round 4
// baseline (speedup 1.0000x reference)
#include <cuda_runtime.h>

// Problem constants
static constexpr int B_DIM = 256;
static constexpr int N_DIM = 65536;
static constexpr int BN    = B_DIM * N_DIM;          // 16,777,216
static constexpr int BN4   = BN / 4;                 // 4,194,304 float4 per tensor
static constexpr int N4    = N_DIM / 4;              // 16,384 float4 in row 0

static constexpr int THREADS = 256;
static constexpr int ILP     = 4;
static constexpr int CHUNK   = THREADS * ILP;        // 1024 float4 per block
static constexpr int BLOCKS  = BN4 / CHUNK;          // 4096
static constexpr int ROW0_BLOCKS = N4 / CHUNK;       // 16 (exact, whole blocks)

// LIF-AdEx parameters (defaults from reference)
#define TAU_SYN_INV   0.5f
#define TAU_MEM_INV   0.5f
#define V_TH          1.0f
#define V_PEAK        30.0f
#define INHIBITION    (-5.0f)

// Elementwise step — single definition used by both the winner scan and the
// output pass, so row-0 spike decisions are bit-identical.
__device__ __forceinline__ void lif_step(float x, float v, float i, float w,
                                         float& z, float& v_out, float& i_new,
                                         float& w_new, float& v_before) {
    i_new = fmaf(TAU_SYN_INV, x - i, i);                 // i + 0.5*(x - i)
    float e = __expf(v - V_TH);                          // delta_t*exp((v-v_th)/delta_t)
    float s = e + i_new - w - v;                         // -(v-v_rest) + e + i_new - w
    float vn = fmaf(TAU_MEM_INV, s, v);                  // v + 0.5*s
    w_new = 0.5f * w;                                    // a_param = 0
    v_before = vn;
    bool spike = (vn >= V_PEAK);
    z = spike ? 1.0f : 0.0f;
    v_out = spike ? 0.0f : vn;                           // v_reset=0, b_param=0
}

__device__ __forceinline__ unsigned long long
umax64(unsigned long long a, unsigned long long b) { return a > b ? a : b; }

// Winner key: upper 32 bits = float bits of v_before (v_before >= 30 > 0 when
// spiked, so raw positive-float bits are order-preserving); lower 32 bits =
// 0xFFFFFFFF - col so max picks the LOWEST column on value ties (jnp.argmax).
// key == 0 <=> no spike in row 0.
__device__ __forceinline__ unsigned long long
winner_key(float vb, unsigned col) {
    return ((unsigned long long)__float_as_uint(vb) << 32) |
           (unsigned long long)(0xFFFFFFFFu - col);
}

// Single fused kernel. The 16 row-0 blocks each redundantly scan all of row 0
// (1 MB, L2-resident after first touch) to compute the SAME winner key
// deterministically — no second kernel, no atomics, no device globals.
// Streaming phase is the R2 per-chunk load->compute->store body (regs ~40).
__global__ void __launch_bounds__(THREADS)
k_fused(const float4* __restrict__ x,
        const float4* __restrict__ v,
        const float4* __restrict__ i,
        const float4* __restrict__ w,
        float4* __restrict__ out) {
    const int  base = blockIdx.x * CHUNK + threadIdx.x;
    const bool row0 = (blockIdx.x < ROW0_BLOCKS);

    __shared__ unsigned long long s_key;

    if (row0) {
        // Full row-0 winner scan: 64 float4 per thread, sequential loop
        // (low register pressure; cost hidden behind the other 4080 blocks).
        unsigned long long best = 0ULL;
        for (int t = threadIdx.x; t < N4; t += THREADS) {
            float4 xf = x[t], vf = v[t], if4 = i[t], wf = w[t];
            float xs[4] = {xf.x, xf.y, xf.z, xf.w};
            float vs[4] = {vf.x, vf.y, vf.z, vf.w};
            float is[4] = {if4.x, if4.y, if4.z, if4.w};
            float ws[4] = {wf.x, wf.y, wf.z, wf.w};
#pragma unroll
            for (int k = 0; k < 4; k++) {
                float z, vo, in, wn, vb;
                lif_step(xs[k], vs[k], is[k], ws[k], z, vo, in, wn, vb);
                if (vb >= V_PEAK)
                    best = umax64(best, winner_key(vb, (unsigned)(t * 4 + k)));
            }
        }
        // warp reduce
#pragma unroll
        for (int o = 16; o > 0; o >>= 1)
            best = umax64(best, __shfl_down_sync(0xFFFFFFFFu, best, o));
        // cross-warp reduce (8 warps)
        __shared__ unsigned long long s_warp[THREADS / 32];
        int wid = threadIdx.x >> 5, lid = threadIdx.x & 31;
        if (lid == 0) s_warp[wid] = best;
        __syncthreads();
        if (threadIdx.x < 32) {
            unsigned long long kk =
                (threadIdx.x < THREADS / 32) ? s_warp[threadIdx.x] : 0ULL;
#pragma unroll
            for (int o = 4; o > 0; o >>= 1)
                kk = umax64(kk, __shfl_down_sync(0xFFFFFFFFu, kk, o));
            if (threadIdx.x == 0) s_key = kk;
        }
        __syncthreads();
    }

    unsigned long long key = 0ULL;
    unsigned winner = 0xFFFFFFFFu;
    if (row0) {
        key = s_key;
        winner = 0xFFFFFFFFu - (unsigned)(key & 0xFFFFFFFFull);
    }

    // ---- streaming pass: per-chunk load -> compute -> store (R2 body) ----
#pragma unroll
    for (int c = 0; c < ILP; c++) {
        const int t = base + c * THREADS;                // coalesced in warp

        float4 xf = __ldcs(&x[t]), vf = __ldcs(&v[t]);
        float4 if4 = __ldcs(&i[t]), wf = __ldcs(&w[t]);
        float xs[4] = {xf.x, xf.y, xf.z, xf.w};
        float vs[4] = {vf.x, vf.y, vf.z, vf.w};
        float is[4] = {if4.x, if4.y, if4.z, if4.w};
        float ws[4] = {wf.x, wf.y, wf.z, wf.w};

        float zo[4], vo[4], io[4], wo[4];
#pragma unroll
        for (int k = 0; k < 4; k++) {
            float vb;
            lif_step(xs[k], vs[k], is[k], ws[k], zo[k], vo[k], io[k], wo[k], vb);
        }

        if (row0 && key != 0ULL) {                       // any_spike0
            int col = t * 4;
#pragma unroll
            for (int k = 0; k < 4; k++) {
                if ((unsigned)(col + k) != winner) {     // inhibit all but winner
                    vo[k] = INHIBITION;
                    wo[k] = 0.0f;
                }
            }
        }

        __stcs(&out[t],           make_float4(zo[0], zo[1], zo[2], zo[3]));
        __stcs(&out[BN4 + t],     make_float4(vo[0], vo[1], vo[2], vo[3]));
        __stcs(&out[2 * BN4 + t], make_float4(io[0], io[1], io[2], io[3]));
        __stcs(&out[3 * BN4 + t], make_float4(wo[0], wo[1], wo[2], wo[3]));
    }
}

extern "C" void kernel_launch(void* const* d_in, const int* in_sizes, int n_in,
                              void* d_out, int out_size) {
    const float4* x = (const float4*)d_in[0];
    const float4* v = (const float4*)d_in[1];
    const float4* i = (const float4*)d_in[2];
    const float4* w = (const float4*)d_in[3];
    float4* out = (float4*)d_out;

    k_fused<<<BLOCKS, THREADS>>>(x, v, i, w, out);
}

// round 5
// speedup vs baseline: 1.1248x; 1.1248x over previous
#include <cuda_runtime.h>

// Problem constants
static constexpr int B_DIM = 256;
static constexpr int N_DIM = 65536;
static constexpr int BN    = B_DIM * N_DIM;          // 16,777,216
static constexpr int BN4   = BN / 4;                 // 4,194,304 float4 per tensor
static constexpr int N4    = N_DIM / 4;              // 16,384 float4 in row 0

static constexpr int THREADS = 256;
static constexpr int ILP     = 4;
static constexpr int CHUNK   = THREADS * ILP;        // 1024 float4 per block
static constexpr int BLOCKS  = BN4 / CHUNK;          // 4096
static constexpr int ROW0_BLOCKS = N4 / CHUNK;       // 16 (exact, whole blocks)

// LIF-AdEx parameters (defaults from reference)
#define TAU_SYN_INV   0.5f
#define TAU_MEM_INV   0.5f
#define V_TH          1.0f
#define V_PEAK        30.0f
#define INHIBITION    (-5.0f)

// Cross-block state for the row-0 fixup. g_partial is written UNCONDITIONALLY
// by every row-0 block each replay; g_count is incremented by each row-0 block
// and reset to 0 by the fixup block before kernel end -> every graph replay
// starts from g_count==0. No init kernel needed.
__device__ unsigned long long g_partial[ROW0_BLOCKS];
__device__ int g_count = 0;

// Elementwise step (identical everywhere so spike decisions are bit-exact).
__device__ __forceinline__ void lif_step(float x, float v, float i, float w,
                                         float& z, float& v_out, float& i_new,
                                         float& w_new, float& v_before) {
    i_new = fmaf(TAU_SYN_INV, x - i, i);                 // i + 0.5*(x - i)
    float e = __expf(v - V_TH);                          // delta_t*exp((v-v_th)/delta_t)
    float s = e + i_new - w - v;                         // -(v-v_rest) + e + i_new - w
    float vn = fmaf(TAU_MEM_INV, s, v);                  // v + 0.5*s
    w_new = 0.5f * w;                                    // a_param = 0
    v_before = vn;
    bool spike = (vn >= V_PEAK);
    z = spike ? 1.0f : 0.0f;
    v_out = spike ? 0.0f : vn;                           // v_reset=0, b_param=0
}

__device__ __forceinline__ unsigned long long
umax64(unsigned long long a, unsigned long long b) { return a > b ? a : b; }

// Winner key: upper 32 = float bits of v_before (>= 30 > 0 when spiked, so raw
// bits are order-preserving); lower 32 = 0xFFFFFFFF - col so max picks the
// LOWEST column on ties (jnp.argmax). key == 0 <=> no spike in row 0.
__device__ __forceinline__ unsigned long long
winner_key(float vb, unsigned col) {
    return ((unsigned long long)__float_as_uint(vb) << 32) |
           (unsigned long long)(0xFFFFFFFFu - col);
}

__global__ void __launch_bounds__(THREADS)
k_fused(const float4* __restrict__ x,
        const float4* __restrict__ v,
        const float4* __restrict__ i,
        const float4* __restrict__ w,
        float4* __restrict__ out) {
    const int  base = blockIdx.x * CHUNK + threadIdx.x;
    const bool row0 = (blockIdx.x < ROW0_BLOCKS);

    // ---- streaming pass (R2 body): per-chunk load -> compute -> store.
    // Row-0 blocks store WITHOUT inhibition and track their partial winner.
    unsigned long long best = 0ULL;

#pragma unroll
    for (int c = 0; c < ILP; c++) {
        const int t = base + c * THREADS;                // coalesced in warp

        float4 xf = __ldcs(&x[t]), vf = __ldcs(&v[t]);
        float4 if4 = __ldcs(&i[t]), wf = __ldcs(&w[t]);
        float xs[4] = {xf.x, xf.y, xf.z, xf.w};
        float vs[4] = {vf.x, vf.y, vf.z, vf.w};
        float is[4] = {if4.x, if4.y, if4.z, if4.w};
        float ws[4] = {wf.x, wf.y, wf.z, wf.w};

        float zo[4], vo[4], io[4], wo[4];
#pragma unroll
        for (int k = 0; k < 4; k++) {
            float vb;
            lif_step(xs[k], vs[k], is[k], ws[k], zo[k], vo[k], io[k], wo[k], vb);
            if (row0 && vb >= V_PEAK)
                best = umax64(best, winner_key(vb, (unsigned)(t * 4 + k)));
        }

        __stcs(&out[t],           make_float4(zo[0], zo[1], zo[2], zo[3]));
        __stcs(&out[BN4 + t],     make_float4(vo[0], vo[1], vo[2], vo[3]));
        __stcs(&out[2 * BN4 + t], make_float4(io[0], io[1], io[2], io[3]));
        __stcs(&out[3 * BN4 + t], make_float4(wo[0], wo[1], wo[2], wo[3]));
    }

    if (!row0) return;

    // ---- row-0 blocks: publish partial winner, last arriver does the fixup.
    __shared__ unsigned long long s_warp[THREADS / 32];
    __shared__ int s_arrival;
    __shared__ unsigned long long s_key;

    // block reduce best
#pragma unroll
    for (int o = 16; o > 0; o >>= 1)
        best = umax64(best, __shfl_down_sync(0xFFFFFFFFu, best, o));
    int wid = threadIdx.x >> 5, lid = threadIdx.x & 31;
    if (lid == 0) s_warp[wid] = best;
    __syncthreads();
    if (threadIdx.x == 0) {
        unsigned long long kk = s_warp[0];
#pragma unroll
        for (int j = 1; j < THREADS / 32; j++) kk = umax64(kk, s_warp[j]);
        g_partial[blockIdx.x] = kk;                      // unconditional write
        __threadfence();                                 // publish before arrive
        s_arrival = atomicAdd(&g_count, 1);
    }
    __syncthreads();

    if (s_arrival != ROW0_BLOCKS - 1) return;            // not the last arriver

    // ---- fixup block: all 16 partials are published and all row-0 streaming
    // stores are visible (each preceded its block's threadfence+arrive).
    if (threadIdx.x == 0) {
        __threadfence();                                 // acquire
        unsigned long long kk = 0ULL;
#pragma unroll
        for (int j = 0; j < ROW0_BLOCKS; j++)
            kk = umax64(kk, __ldcg(&g_partial[j]));      // L2, bypass L1
        s_key = kk;
        g_count = 0;                                     // reset for next replay
    }
    __syncthreads();

    unsigned long long key = s_key;
    if (key == 0ULL) return;                             // no spike -> no inhibition

    const unsigned winner = 0xFFFFFFFFu - (unsigned)(key & 0xFFFFFFFFull);
    const int wt4 = (int)(winner >> 2);                  // float4 index holding winner

    const float4 inh4  = make_float4(INHIBITION, INHIBITION, INHIBITION, INHIBITION);
    const float4 zero4 = make_float4(0.0f, 0.0f, 0.0f, 0.0f);
    for (int t = threadIdx.x; t < N4; t += THREADS) {
        if (t != wt4) {
            out[BN4 + t]     = inh4;                     // v[0, :] = -5
            out[3 * BN4 + t] = zero4;                    // w[0, :] = 0
        }
    }
    // the float4 containing the winner: scalar-patch the 3 non-winner lanes
    if (threadIdx.x < 4) {
        unsigned col = (unsigned)(wt4 * 4 + threadIdx.x);
        if (col != winner) {
            float* outf = (float*)out;
            outf[(size_t)(BN4 + wt4) * 4 + threadIdx.x]     = INHIBITION;
            outf[(size_t)(3 * BN4 + wt4) * 4 + threadIdx.x] = 0.0f;
        }
    }
}

extern "C" void kernel_launch(void* const* d_in, const int* in_sizes, int n_in,
                              void* d_out, int out_size) {
    const float4* x = (const float4*)d_in[0];
    const float4* v = (const float4*)d_in[1];
    const float4* i = (const float4*)d_in[2];
    const float4* w = (const float4*)d_in[3];
    float4* out = (float4*)d_out;

    k_fused<<<BLOCKS, THREADS>>>(x, v, i, w, out);
}